// round 8
// baseline (speedup 1.0000x reference)
#include <cuda_runtime.h>
#include <math.h>
#include <float.h>

// ---------------------------------------------------------------------------
// AngularLoss: loss = logsumexp_i( 4*t2*dot(a_i+p_i, n_i) - 2*(1+t2)*dot(a_i,p_i) )
// N = 262144 rows, D = 128. HBM-streaming reduction (384 MiB -> 1 float).
//
// R8: lane remap — 8 lanes per row, 4 rows per warp-tile.
//   * per tile: 12 LDG.128 (each = 4 full 128B lines, identical density),
//     3 SHFLs total (vs 20), 1 branchless LSE update per lane (vs 4 expf+branch)
//   * every row's exp contributed by 8 lanes -> uniform 8x overcount,
//     corrected with  loss = M + log(S) - ln(8)
//   * loads within a tile are independent -> compiler batches without the
//     register blowup that killed R3/R6 unroll attempts
// Fused last-block-done finish (deterministic fixed-order fold, ticket resets).
// ---------------------------------------------------------------------------

#define P1_BLOCKS 1184
#define P1_THREADS 256
#define WARPS_PER_BLOCK (P1_THREADS / 32)

__device__ float2 g_partials[P1_BLOCKS];
__device__ unsigned int g_ticket;   // zero-init; self-resets each call

__device__ __forceinline__ void lse_combine(float& m, float& s, float om, float os) {
    float nm = fmaxf(m, om);
    s = s * __expf(m - nm) + os * __expf(om - nm);
    m = nm;
}

__global__ void __launch_bounds__(P1_THREADS)
angular_fused(const float* __restrict__ A,
              const float* __restrict__ P,
              const float* __restrict__ Ng,
              const int*   __restrict__ alpha_raw,
              float* __restrict__ out,
              int N)
{
    int raw = alpha_raw[0];
    float alpha = (raw > 1000000 || raw < -1000000) ? __int_as_float(raw) : (float)raw;
    float ang = alpha * (3.14159265358979323846f / 180.0f);
    float t  = tanf(ang);
    float t2 = t * t;
    float c1 = 4.0f * t2;
    float c2 = -2.0f * (1.0f + t2);

    const float4* A4 = (const float4*)A;
    const float4* P4 = (const float4*)P;
    const float4* N4 = (const float4*)Ng;

    int lane = threadIdx.x & 31;
    int warp = threadIdx.x >> 5;
    int gwarp  = blockIdx.x * WARPS_PER_BLOCK + warp;
    int nwarps = P1_BLOCKS * WARPS_PER_BLOCK;

    int rsub  = lane >> 3;   // row within tile (0..3)
    int chunk = lane & 7;    // float4-chunk group (0..7)

    float m = -FLT_MAX;
    float s = 0.0f;

    int ntiles = N >> 2;     // 4 rows per tile

    for (int tile = gwarp; tile < ntiles; tile += nwarps) {
        int row = tile * 4 + rsub;
        // float4 index of this lane's first element in its row
        size_t base = (size_t)row * 32 + chunk;

        float ap = 0.0f, apn = 0.0f;
        #pragma unroll
        for (int i = 0; i < 4; i++) {
            float4 a = A4[base + i * 8];
            float4 p = P4[base + i * 8];
            float4 n = N4[base + i * 8];
            ap  += a.x * p.x + a.y * p.y + a.z * p.z + a.w * p.w;
            apn += (a.x + p.x) * n.x + (a.y + p.y) * n.y
                 + (a.z + p.z) * n.z + (a.w + p.w) * n.w;
        }

        // per-lane partial of f; reduce within the 8-lane row group
        float f = c1 * apn + c2 * ap;
        f += __shfl_xor_sync(0xFFFFFFFFu, f, 1);
        f += __shfl_xor_sync(0xFFFFFFFFu, f, 2);
        f += __shfl_xor_sync(0xFFFFFFFFu, f, 4);
        // every lane now holds its own row's f (8 copies per row)

        // branchless online LSE (f differs across row groups -> no divergence)
        float nm = fmaxf(m, f);
        s = s * __expf(m - nm) + __expf(f - nm);
        m = nm;
    }

    // Tail rows (N % 4) — none for this shape; weighted 8/32 to stay uniform.
    for (int row = ntiles * 4 + gwarp; row < N; row += nwarps) {
        size_t base = (size_t)row * 32 + lane;
        float4 a = A4[base], p = P4[base], n = N4[base];
        float ap  = a.x * p.x + a.y * p.y + a.z * p.z + a.w * p.w;
        float apn = (a.x + p.x) * n.x + (a.y + p.y) * n.y
                  + (a.z + p.z) * n.z + (a.w + p.w) * n.w;
        float f = c1 * apn + c2 * ap;
        #pragma unroll
        for (int o = 16; o > 0; o >>= 1)
            f += __shfl_xor_sync(0xFFFFFFFFu, f, o);
        float nm = fmaxf(m, f);
        s = s * __expf(m - nm) + 0.25f * __expf(f - nm);  // 8/32 weight
        m = nm;
    }

    // Warp reduce (m,s) pairs, then block reduce via shared.
    #pragma unroll
    for (int o = 16; o > 0; o >>= 1) {
        float om = __shfl_xor_sync(0xFFFFFFFFu, m, o);
        float os = __shfl_xor_sync(0xFFFFFFFFu, s, o);
        lse_combine(m, s, om, os);
    }

    __shared__ float sm[WARPS_PER_BLOCK];
    __shared__ float ss[WARPS_PER_BLOCK];
    __shared__ bool s_last;
    if (lane == 0) { sm[warp] = m; ss[warp] = s; }
    __syncthreads();

    if (threadIdx.x == 0) {
        float M = -FLT_MAX, S = 0.0f;
        #pragma unroll
        for (int w = 0; w < WARPS_PER_BLOCK; w++)
            lse_combine(M, S, sm[w], ss[w]);
        g_partials[blockIdx.x] = make_float2(M, S);
        __threadfence();
        unsigned int t_old = atomicAdd(&g_ticket, 1u);
        s_last = (t_old == (unsigned int)(P1_BLOCKS - 1));
    }
    __syncthreads();

    if (!s_last) return;

    // Last block: fold all block partials in fixed index order (deterministic).
    {
        int tid = threadIdx.x;
        float fm = -FLT_MAX, fs = 0.0f;
        for (int i = tid; i < P1_BLOCKS; i += P1_THREADS) {
            float2 pp = g_partials[i];
            lse_combine(fm, fs, pp.x, pp.y);
        }
        #pragma unroll
        for (int o = 16; o > 0; o >>= 1) {
            float om = __shfl_xor_sync(0xFFFFFFFFu, fm, o);
            float os = __shfl_xor_sync(0xFFFFFFFFu, fs, o);
            lse_combine(fm, fs, om, os);
        }
        __shared__ float fsm[WARPS_PER_BLOCK];
        __shared__ float fss[WARPS_PER_BLOCK];
        if (lane == 0) { fsm[warp] = fm; fss[warp] = fs; }
        __syncthreads();
        if (threadIdx.x == 0) {
            float M = -FLT_MAX, S = 0.0f;
            #pragma unroll
            for (int w = 0; w < WARPS_PER_BLOCK; w++)
                lse_combine(M, S, fsm[w], fss[w]);
            // every row counted 8x (8 lanes share each row's f) -> subtract ln 8
            out[0] = M + logf(S) - 2.0794415416798357f;
            g_ticket = 0;   // reset for next graph replay
        }
    }
}

extern "C" void kernel_launch(void* const* d_in, const int* in_sizes, int n_in,
                              void* d_out, int out_size)
{
    const float* A  = (const float*)d_in[0];
    const float* P  = (const float*)d_in[1];
    const float* Ng = (const float*)d_in[2];
    const int*   al = (const int*)d_in[3];
    float* out = (float*)d_out;

    int N = in_sizes[0] / 128;   // D = 128

    angular_fused<<<P1_BLOCKS, P1_THREADS>>>(A, P, Ng, al, out, N);
}